// round 16
// baseline (speedup 1.0000x reference)
#include <cuda_runtime.h>
#include <cuda_fp16.h>
#include <cstdint>

#define N_NODES 50000
#define N_EDGES 800000
#define N_GRAPHS 1000
#define X_DIM 128
#define HIDDEN 256
#define N_LAYERS 3
#define N_CLASS 10
#define HN (N_NODES * HIDDEN)

typedef __half fp16;

// ---------------- device scratch ----------------
__device__ float g_h0[HN];                           // f32 activations (final layer only)
__device__ fp16  g_h0b[HN], g_h1b[HN];               // fp16 activations (ping/pong)
__device__ fp16  g_aggb[HN];                         // fp16 aggregated messages
__device__ fp16  g_scr[HN];                          // fp16 partial (h @ W_r)
__device__ fp16  g_xb[N_NODES * X_DIM];
__device__ fp16  g_wte[HIDDEN * X_DIM];              // W_enc^T [n][k]
__device__ fp16  g_wtl[N_LAYERS * HIDDEN * HIDDEN];
__device__ fp16  g_wtr[N_LAYERS * HIDDEN * HIDDEN];
__device__ int   g_deg[N_NODES];
__device__ int   g_off[N_NODES];
__device__ int   g_cur[N_NODES];
__device__ float g_invdeg[N_NODES];
__device__ int   g_ecnt;
__device__ int   g_src_sorted[N_EDGES];
__device__ float g_att_sorted[N_EDGES];
__device__ int   g_gstart[N_GRAPHS];
__device__ int   g_gend[N_GRAPHS];

// ---------------- helpers ----------------
__device__ __forceinline__ uint32_t smem_u32(const void* p) {
    uint32_t a;
    asm("{ .reg .u64 t; cvta.to.shared.u64 t, %1; cvt.u32.u64 %0, t; }" : "=r"(a) : "l"(p));
    return a;
}

__global__ void zero_int_kernel(int* p, int n) {
    int i = blockIdx.x * blockDim.x + threadIdx.x;
    if (i < n) p[i] = 0;
}
__global__ void degree_kernel(const int* __restrict__ dst) {
    int e = blockIdx.x * blockDim.x + threadIdx.x;
    if (e < N_EDGES) atomicAdd(&g_deg[dst[e]], 1);
}
// order-free offset allocation (CSR segment placement need not be ordered)
__global__ void offsets_kernel() {
    int i = blockIdx.x * blockDim.x + threadIdx.x;
    if (i < N_NODES) {
        int d = g_deg[i];
        int o = atomicAdd(&g_ecnt, d);
        g_off[i] = o;
        g_cur[i] = o;
        g_invdeg[i] = 1.0f / (float)(d > 1 ? d : 1);
    }
}
__global__ void fill_csr_kernel(const int* __restrict__ src, const int* __restrict__ dst,
                                const float* __restrict__ atten) {
    int e = blockIdx.x * blockDim.x + threadIdx.x;
    if (e < N_EDGES) {
        int d = dst[e];
        int pos = atomicAdd(&g_cur[d], 1);
        g_src_sorted[pos] = src[e];
        g_att_sorted[pos] = atten[e];
    }
}
__global__ void gbounds_init_kernel() {
    int g = blockIdx.x * blockDim.x + threadIdx.x;
    if (g < N_GRAPHS) { g_gstart[g] = N_NODES; g_gend[g] = 0; }
}
__global__ void gbounds_kernel(const int* __restrict__ batch) {
    int i = blockIdx.x * blockDim.x + threadIdx.x;
    if (i < N_NODES) {
        int b = batch[i];
        atomicMin(&g_gstart[b], i);
        atomicMax(&g_gend[b], i + 1);
    }
}
__global__ void split_x_kernel(const float* __restrict__ x) {
    int i = blockIdx.x * blockDim.x + threadIdx.x;
    if (i < N_NODES * X_DIM) g_xb[i] = __float2half(x[i]);
}
// transpose + convert weights: src [L][K][N] -> dst [L][N][K] fp16
__global__ void wsplit_kernel(const float* __restrict__ W, fp16* __restrict__ o,
                              int K, int N, int L) {
    int idx = blockIdx.x * blockDim.x + threadIdx.x;
    int total = L * K * N;
    if (idx >= total) return;
    int l = idx / (K * N);
    int r = idx - l * K * N;
    int k = r / N;
    int n = r - k * N;
    o[(l * N + n) * K + k] = __float2half(W[idx]);
}

// ---------------- aggregate body (1 warp per node, uint4 per lane) ----------------
__device__ __forceinline__ void aggregate_node(const fp16* __restrict__ hb, int node, int lane) {
    if (node >= N_NODES) return;
    int start = g_off[node];
    int d = g_deg[node];
    const int* __restrict__ sp = g_src_sorted + start;
    const float* __restrict__ ap = g_att_sorted + start;
    float acc[8];
#pragma unroll
    for (int j = 0; j < 8; j++) acc[j] = 0.f;

    auto accum = [&](float a, uint4 v) {
        const __half2* p2 = reinterpret_cast<const __half2*>(&v);
#pragma unroll
        for (int j = 0; j < 4; j++) {
            float2 f = __half22float2(p2[j]);
            acc[2 * j + 0] += a * f.x;
            acc[2 * j + 1] += a * f.y;
        }
    };

    int e = 0;
    for (; e + 4 <= d; e += 4) {
        int s0 = __ldg(sp + e + 0), s1 = __ldg(sp + e + 1);
        int s2 = __ldg(sp + e + 2), s3 = __ldg(sp + e + 3);
        float a0 = __ldg(ap + e + 0), a1 = __ldg(ap + e + 1);
        float a2 = __ldg(ap + e + 2), a3 = __ldg(ap + e + 3);
        uint4 v0 = *reinterpret_cast<const uint4*>(hb + (size_t)s0 * HIDDEN + lane * 8);
        uint4 v1 = *reinterpret_cast<const uint4*>(hb + (size_t)s1 * HIDDEN + lane * 8);
        uint4 v2 = *reinterpret_cast<const uint4*>(hb + (size_t)s2 * HIDDEN + lane * 8);
        uint4 v3 = *reinterpret_cast<const uint4*>(hb + (size_t)s3 * HIDDEN + lane * 8);
        accum(a0, v0); accum(a1, v1); accum(a2, v2); accum(a3, v3);
    }
    for (; e < d; e++) {
        int s = __ldg(sp + e);
        float a = __ldg(ap + e);
        uint4 v = *reinterpret_cast<const uint4*>(hb + (size_t)s * HIDDEN + lane * 8);
        accum(a, v);
    }

    float id = g_invdeg[node];
    fp16 h8[8];
#pragma unroll
    for (int j = 0; j < 8; j++) h8[j] = __float2half(acc[j] * id);
    *reinterpret_cast<uint4*>(g_aggb + (size_t)node * HIDDEN + lane * 8) =
        *reinterpret_cast<uint4*>(h8);
}

// ---------------- GEMM machinery (R8/R15-proven shape) ----------------
#define ROWS_S 40                       // 80B row stride (5x16B), ldmatrix conflict-free
#define OPER_B (128 * ROWS_S * 2)       // 10240 B per operand per stage
#define STAGE_B (2 * OPER_B)            // 20480 B per stage
#define NSTAGE 4
#define GEMM_SMEM (NSTAGE * STAGE_B)    // 81920 B
#define NGEMM_T 782                     // 2 x 391 tiles

__device__ __forceinline__ void ldm_x4(uint32_t* r, uint32_t addr) {
    asm volatile("ldmatrix.sync.aligned.m8n8.x4.shared.b16 {%0,%1,%2,%3}, [%4];"
                 : "=r"(r[0]), "=r"(r[1]), "=r"(r[2]), "=r"(r[3]) : "r"(addr));
}
__device__ __forceinline__ void mma_fp16(float* d, const uint32_t* a, uint32_t b0, uint32_t b1) {
    asm volatile(
        "mma.sync.aligned.m16n8k16.row.col.f32.f16.f16.f32 "
        "{%0,%1,%2,%3}, {%4,%5,%6,%7}, {%8,%9}, {%0,%1,%2,%3};"
        : "+f"(d[0]), "+f"(d[1]), "+f"(d[2]), "+f"(d[3])
        : "r"(a[0]), "r"(a[1]), "r"(a[2]), "r"(a[3]), "r"(b0), "r"(b1));
}
__device__ __forceinline__ void cp_async16(uint32_t dst, const void* src, int srcsize) {
    asm volatile("cp.async.cg.shared.global [%0], [%1], 16, %2;"
                 :: "r"(dst), "l"(src), "r"(srcsize) : "memory");
}
#define CP_COMMIT() asm volatile("cp.async.commit_group;" ::: "memory")
#define CP_WAIT(n)  asm volatile("cp.async.wait_group %0;" :: "n"(n) : "memory")

// single-source GEMM mainloop into d[2][8][4]; A=[M][K], B=[256][K] K-major
template <int K>
__device__ __forceinline__ void gemm_mainloop(
    const fp16* __restrict__ A, const fp16* __restrict__ B,
    uint32_t sbase, int m0, int n0, int M, float d[2][8][4])
{
    const int tid = threadIdx.x;
    const int lane = tid & 31, wid = tid >> 5;
    const int warp_m = wid & 3, warp_n = wid >> 2;
    constexpr int NCH = K / 32;

    auto load_chunk = [&](int buf, int c) {
        const int k0 = c * 32;
        const uint32_t sb = sbase + buf * STAGE_B;
#pragma unroll
        for (int h = 0; h < 2; h++) {
            int u = tid + h * 256;
            int row = u >> 2, seg = u & 3;
            int grow = m0 + row;
            int valid = grow < M;
            const fp16* ga = A + (size_t)(valid ? grow : 0) * K + k0 + seg * 8;
            cp_async16(sb + (row * ROWS_S + seg * 8) * 2, ga, valid ? 16 : 0);
            const fp16* gb = B + (size_t)(n0 + row) * K + k0 + seg * 8;
            cp_async16(sb + OPER_B + (row * ROWS_S + seg * 8) * 2, gb, 16);
        }
        CP_COMMIT();
    };

    load_chunk(0, 0);
    load_chunk(1, 1);
    load_chunk(2, 2);

    const uint32_t aBase = ((warp_m * 32 + (lane & 15)) * ROWS_S + (lane >> 4) * 8) * 2;
    const uint32_t bBase = ((warp_n * 64 + (lane & 15)) * ROWS_S + (lane >> 4) * 8) * 2;

    for (int c = 0; c < NCH; c++) {
        CP_WAIT(2);
        __syncthreads();
        if (c + 3 < NCH) load_chunk((c + 3) & 3, c + 3);
        else CP_COMMIT();

        const int buf = c & 3;
        const uint32_t aB = sbase + buf * STAGE_B + aBase;
        const uint32_t bB = sbase + buf * STAGE_B + OPER_B + bBase;
#pragma unroll
        for (int ks = 0; ks < 2; ks++) {
            uint32_t afr[2][4];
#pragma unroll
            for (int mi = 0; mi < 2; mi++)
                ldm_x4(afr[mi], aB + ks * 32 + mi * 16 * ROWS_S * 2);
#pragma unroll
            for (int p = 0; p < 4; p++) {
                uint32_t br[4];
                ldm_x4(br, bB + ks * 32 + p * 16 * ROWS_S * 2);
#pragma unroll
                for (int mi = 0; mi < 2; mi++) {
                    mma_fp16(d[mi][2 * p + 0], afr[mi], br[0], br[2]);
                    mma_fp16(d[mi][2 * p + 1], afr[mi], br[1], br[3]);
                }
            }
        }
    }
}

// fused kernel: 1-in-9 blocks do h@W_r GEMM tile -> fp16 scratch; 8-in-9 aggregate
__global__ __launch_bounds__(256) void fused_gr_agg(
    const fp16* __restrict__ h, const fp16* __restrict__ wr, int M)
{
    extern __shared__ char dsmem[];
    const int grp = blockIdx.x / 9, rem = blockIdx.x % 9;
    if (rem == 0) {
        // GEMM tile grp (grp < NGEMM_T)
        const int m0 = (grp >> 1) * 128, n0 = (grp & 1) * 128;
        float d[2][8][4];
#pragma unroll
        for (int i = 0; i < 2; i++)
#pragma unroll
            for (int j = 0; j < 8; j++)
#pragma unroll
                for (int q = 0; q < 4; q++) d[i][j][q] = 0.f;
        gemm_mainloop<HIDDEN>(h, wr, smem_u32(dsmem), m0, n0, M, d);
        const int lane = threadIdx.x & 31, wid = threadIdx.x >> 5;
        const int warp_m = wid & 3, warp_n = wid >> 2;
#pragma unroll
        for (int mi = 0; mi < 2; mi++) {
            const int rb = m0 + warp_m * 32 + mi * 16 + (lane >> 2);
#pragma unroll
            for (int j = 0; j < 8; j++) {
                const int cb = n0 + warp_n * 64 + j * 8 + (lane & 3) * 2;
#pragma unroll
                for (int half = 0; half < 2; half++) {
                    const int r = rb + half * 8;
                    if (r >= M) continue;
                    fp16 h2[2] = {__float2half(d[mi][j][half * 2 + 0]),
                                  __float2half(d[mi][j][half * 2 + 1])};
                    *reinterpret_cast<uint32_t*>(g_scr + (size_t)r * HIDDEN + cb) =
                        *reinterpret_cast<uint32_t*>(h2);
                }
            }
        }
    } else {
        int node = grp * 64 + (rem - 1) * 8 + (threadIdx.x >> 5);
        aggregate_node(h, node, threadIdx.x & 31);
    }
}

// combine kernel: agg @ W_l (+ scratch) (+ bias) [relu] -> fp16 h' and/or f32 h
template <int K, bool ADDSCR, bool RELU, bool WRITEFP16, bool WRITEF32>
__global__ __launch_bounds__(256, 1) void mma_gemm(
    const fp16* __restrict__ A, const fp16* __restrict__ B,
    const float* __restrict__ bias,
    float* __restrict__ C, fp16* __restrict__ Cb, int M)
{
    extern __shared__ char dsmem[];
    const int m0 = blockIdx.y * 128, n0 = blockIdx.x * 128;
    float d[2][8][4];
#pragma unroll
    for (int i = 0; i < 2; i++)
#pragma unroll
        for (int j = 0; j < 8; j++)
#pragma unroll
            for (int q = 0; q < 4; q++) d[i][j][q] = 0.f;
    gemm_mainloop<K>(A, B, smem_u32(dsmem), m0, n0, M, d);

    const int lane = threadIdx.x & 31, wid = threadIdx.x >> 5;
    const int warp_m = wid & 3, warp_n = wid >> 2;
#pragma unroll
    for (int mi = 0; mi < 2; mi++) {
        const int rb = m0 + warp_m * 32 + mi * 16 + (lane >> 2);
#pragma unroll
        for (int j = 0; j < 8; j++) {
            const int cb = n0 + warp_n * 64 + j * 8 + (lane & 3) * 2;
            const float bx = __ldg(bias + cb), by = __ldg(bias + cb + 1);
#pragma unroll
            for (int half = 0; half < 2; half++) {
                const int r = rb + half * 8;
                if (r >= M) continue;
                float vx = d[mi][j][half * 2 + 0] + bx;
                float vy = d[mi][j][half * 2 + 1] + by;
                if (ADDSCR) {
                    uint32_t sv = *reinterpret_cast<const uint32_t*>(
                        g_scr + (size_t)r * HIDDEN + cb);
                    float2 sf = __half22float2(*reinterpret_cast<__half2*>(&sv));
                    vx += sf.x;
                    vy += sf.y;
                }
                if (RELU) {
                    vx = vx > 0.f ? vx : 0.f;
                    vy = vy > 0.f ? vy : 0.f;
                }
                if (WRITEF32)
                    *reinterpret_cast<float2*>(C + (size_t)r * HIDDEN + cb) = make_float2(vx, vy);
                if (WRITEFP16) {
                    fp16 h2[2] = {__float2half(vx), __float2half(vy)};
                    *reinterpret_cast<uint32_t*>(Cb + (size_t)r * HIDDEN + cb) =
                        *reinterpret_cast<uint32_t*>(h2);
                }
            }
        }
    }
}

// fused pool + head
__global__ void pool_head_kernel(const float* __restrict__ h, const float* __restrict__ W,
                                 const float* __restrict__ b, float* __restrict__ out) {
    __shared__ float sh[HIDDEN];
    int g = blockIdx.x;
    int s = g_gstart[g], e = g_gend[g];
    int c = threadIdx.x;
    float acc = 0.f;
    for (int n = s; n < e; n++) acc += h[(size_t)n * HIDDEN + c];
    sh[c] = acc;
    __syncthreads();
    if (c < N_CLASS) {
        float sum = __ldg(b + c);
#pragma unroll 8
        for (int k = 0; k < HIDDEN; k++) sum += sh[k] * __ldg(W + k * N_CLASS + c);
        out[(size_t)g * N_CLASS + c] = sum;
    }
}

extern "C" void kernel_launch(void* const* d_in, const int* in_sizes, int n_in,
                              void* d_out, int out_size) {
    const float* x        = (const float*)d_in[0];
    const int*   edge_idx = (const int*)d_in[1];
    const int*   batch    = (const int*)d_in[2];
    const float* edge_att = (const float*)d_in[3];
    const float* W_enc    = (const float*)d_in[4];
    const float* b_enc    = (const float*)d_in[5];
    const float* W_l      = (const float*)d_in[6];
    const float* b_l      = (const float*)d_in[7];
    const float* W_r      = (const float*)d_in[8];
    const float* W_out    = (const float*)d_in[9];
    const float* b_out    = (const float*)d_in[10];
    float* out = (float*)d_out;

    const int* src = edge_idx;
    const int* dst = edge_idx + N_EDGES;

    float* h0;
    fp16 *h0b, *h1b, *aggb, *xb, *wte, *wtl, *wtr;
    int *deg, *ecnt;
    cudaGetSymbolAddress((void**)&h0, g_h0);
    cudaGetSymbolAddress((void**)&h0b, g_h0b);
    cudaGetSymbolAddress((void**)&h1b, g_h1b);
    cudaGetSymbolAddress((void**)&aggb, g_aggb);
    cudaGetSymbolAddress((void**)&xb, g_xb);
    cudaGetSymbolAddress((void**)&wte, g_wte);
    cudaGetSymbolAddress((void**)&wtl, g_wtl);
    cudaGetSymbolAddress((void**)&wtr, g_wtr);
    cudaGetSymbolAddress((void**)&deg, g_deg);
    cudaGetSymbolAddress((void**)&ecnt, g_ecnt);

    cudaFuncSetAttribute(fused_gr_agg,
                         cudaFuncAttributeMaxDynamicSharedMemorySize, GEMM_SMEM);
    cudaFuncSetAttribute(mma_gemm<X_DIM, false, false, true, false>,
                         cudaFuncAttributeMaxDynamicSharedMemorySize, GEMM_SMEM);
    cudaFuncSetAttribute(mma_gemm<HIDDEN, true, true, true, false>,
                         cudaFuncAttributeMaxDynamicSharedMemorySize, GEMM_SMEM);
    cudaFuncSetAttribute(mma_gemm<HIDDEN, true, true, false, true>,
                         cudaFuncAttributeMaxDynamicSharedMemorySize, GEMM_SMEM);

    // 1) CSR + graph bounds (order-free offsets, no serial scan)
    zero_int_kernel<<<(N_NODES + 255) / 256, 256>>>(deg, N_NODES);
    zero_int_kernel<<<1, 32>>>(ecnt, 1);
    degree_kernel<<<(N_EDGES + 255) / 256, 256>>>(dst);
    offsets_kernel<<<(N_NODES + 255) / 256, 256>>>();
    fill_csr_kernel<<<(N_EDGES + 255) / 256, 256>>>(src, dst, edge_att);
    gbounds_init_kernel<<<(N_GRAPHS + 255) / 256, 256>>>();
    gbounds_kernel<<<(N_NODES + 255) / 256, 256>>>(batch);

    // 2) operand prep
    split_x_kernel<<<(N_NODES * X_DIM + 255) / 256, 256>>>(x);
    wsplit_kernel<<<(X_DIM * HIDDEN + 255) / 256, 256>>>(W_enc, wte, X_DIM, HIDDEN, 1);
    wsplit_kernel<<<(N_LAYERS * HIDDEN * HIDDEN + 255) / 256, 256>>>(W_l, wtl, HIDDEN, HIDDEN, N_LAYERS);
    wsplit_kernel<<<(N_LAYERS * HIDDEN * HIDDEN + 255) / 256, 256>>>(W_r, wtr, HIDDEN, HIDDEN, N_LAYERS);

    const int MT = (N_NODES + 127) / 128;   // 391
    dim3 grid2(2, MT);

    // 3) encoder: h0b = fp16(x @ W_enc + b_enc)
    mma_gemm<X_DIM, false, false, true, false><<<grid2, 256, GEMM_SMEM>>>(
        xb, wte, b_enc, nullptr, h0b, N_NODES);

    // 4) layers: fused (aggregate || h@W_r -> scr), then agg@W_l + scr + bias, relu
    fp16 *hcb = h0b, *hnb = h1b;
    for (int l = 0; l < N_LAYERS; l++) {
        fused_gr_agg<<<NGEMM_T * 9, 256, GEMM_SMEM>>>(
            hcb, wtr + (size_t)l * HIDDEN * HIDDEN, N_NODES);
        const float* bb = b_l + (size_t)l * HIDDEN;
        if (l < N_LAYERS - 1) {
            mma_gemm<HIDDEN, true, true, true, false><<<grid2, 256, GEMM_SMEM>>>(
                aggb, wtl + (size_t)l * HIDDEN * HIDDEN, bb, nullptr, hnb, N_NODES);
        } else {
            mma_gemm<HIDDEN, true, true, false, true><<<grid2, 256, GEMM_SMEM>>>(
                aggb, wtl + (size_t)l * HIDDEN * HIDDEN, bb, h0, nullptr, N_NODES);
        }
        fp16* tb = hcb; hcb = hnb; hnb = tb;
    }

    // 5) fused pool + head
    pool_head_kernel<<<N_GRAPHS, HIDDEN>>>(h0, W_out, b_out, out);
}